// round 15
// baseline (speedup 1.0000x reference)
#include <cuda_runtime.h>
#include <cstdint>

// SpatialPool: fm [B=16, C=512, H=38, W=38] f32 (NCHW)
//   -> out [B, H*W, 9*C] f32, out[b, h*W+w, (di*3+dj)*C + c]
//      = fm[b, c, clamp(h+di-1), clamp(w+dj-1)]  (replicate pad)
//
// R15: split work by neighbor-row di instead of channels. CTA (wh,y,di,b)
// owns ALL 512 channels of ONE loaded row clamp(y-1+di) (43KB smem, same
// footprint/occupancy as R7) and writes 57 chunks x 2KB, each chunk fully
// contiguous from a single warp -> DRAM write granularity 512B -> 2KB.
// Load: R7-style coalesced cp.async; extra row re-reads are L2-resident.

namespace {
constexpr int HH   = 38;
constexpr int C    = 512;
constexpr int NB   = 9;
constexpr int WT   = 19;         // w positions per CTA
constexpr int LW   = WT + 2;     // 21 local cols incl. halo
constexpr int THREADS = 512;
constexpr int HW   = HH * HH;    // 1444
constexpr int RS4  = NB * C / 4; // 1152 float4 per (b,y,w)
constexpr int NELEM = LW * C;    // 10752 elements per CTA
constexpr int ITERS = NELEM / THREADS;   // 21
constexpr int LSTEP = THREADS % LW;      // 8
constexpr int CSTEP = THREADS / LW;      // 24
}

__device__ __forceinline__ void cp_async4(float* smem_dst, const float* gsrc) {
    uint32_t sa = (uint32_t)__cvta_generic_to_shared(smem_dst);
    asm volatile("cp.async.ca.shared.global [%0], [%1], 4;\n"
                 :: "r"(sa), "l"(gsrc) : "memory");
}

__global__ __launch_bounds__(THREADS, 4)
void spatialpool_kernel(const float* __restrict__ fm, float* __restrict__ out) {
    // logical (l, c) at smP[l*512 + 4*((c>>2)^l) + (c&3)]  (l < 21 < 32)
    __shared__ float smP[LW * C];   // 43,008 B -> 4 CTAs/SM

    const int lane = threadIdx.x & 31;
    const int wid  = threadIdx.x >> 5;

    const int wh = blockIdx.x & 1;
    const int di = blockIdx.x >> 1;        // 0..2 neighbor row
    const int w0 = wh * WT;
    const int y  = blockIdx.y;
    const int b  = blockIdx.z;

    const int yl = min(max(y - 1 + di, 0), HH - 1);
    const float* __restrict__ frow =
        fm + (size_t)b * C * HW + (size_t)yl * HH;

    // ---- Load ONE row: linear sweep idx = c*21 + l, incremental (c,l).
    // Lanes hold consecutive idx -> runs of 21 consecutive floats
    // (coalesced cp.async). Swizzled STS. ----
    {
        int c = threadIdx.x / LW;            // one div
        int l = threadIdx.x - c * LW;
        #pragma unroll 7
        for (int it = 0; it < ITERS; ++it) {
            int xg = min(max(w0 - 1 + l, 0), HH - 1);
            int sw = (l << 9) + ((((c >> 2) ^ l) << 2) | (c & 3));
            cp_async4(&smP[sw], frow + c * HW + xg);
            l += LSTEP; c += CSTEP;
            if (l >= LW) { l -= LW; c += 1; }
        }
    }
    asm volatile("cp.async.wait_all;\n" ::: "memory");
    __syncthreads();

    // ---- Write: warp-per-chunk, chunk = (wl, dj) = 512 floats = 2KB,
    // fully contiguous: 4 independent LDS.128 + 4 STG.128.cs. ----
    float4* __restrict__ out4 = (float4*)out;
    const size_t base4 =
        ((size_t)b * HW + (size_t)y * HH + w0) * (size_t)RS4
        + (size_t)(3 * di) * (C / 4) + lane;

    #pragma unroll 2
    for (int tch = wid; tch < WT * 3; tch += THREADS / 32) {
        int wl = tch / 3;                  // magic-mul
        int dj = tch - 3 * wl;
        int l  = wl + dj;                  // smem position

        const float* __restrict__ sp = &smP[l << 9];
        float4* __restrict__ o =
            &out4[base4 + (size_t)wl * RS4 + dj * (C / 4)];

        #pragma unroll
        for (int j = 0; j < 4; ++j) {
            const float4 v = *(const float4*)
                &sp[((lane + 32 * j) ^ l) << 2];
            __stcs(&o[32 * j], v);
        }
    }
}

extern "C" void kernel_launch(void* const* d_in, const int* in_sizes, int n_in,
                              void* d_out, int out_size) {
    const float* fm = (const float*)d_in[0];
    float* out = (float*)d_out;
    (void)in_sizes; (void)n_in; (void)out_size;

    dim3 grid(2 * 3, HH, 16);   // (6, 38, 16) = 3648 CTAs
    spatialpool_kernel<<<grid, THREADS>>>(fm, out);
}

// round 16
// speedup vs baseline: 1.4454x; 1.4454x over previous
#include <cuda_runtime.h>
#include <cstdint>

// SpatialPool: fm [B=16, C=512, H=38, W=38] f32 (NCHW)
//   -> out [B, H*W, 9*C] f32, out[b, h*W+w, (di*3+dj)*C + c]
//      = fm[b, c, clamp(h+di-1), clamp(w+dj-1)]  (replicate pad)
//
// R16: intra-CTA double-buffered w-subtiles at R7's occupancy. CTA
// (cg, y-pair, b) walks 4 w-subtiles (10,10,10,8 wide); while subtile s
// streams its stores (R7-verbatim write phase: n-major, conflict-free
// LDS.128 + coalesced 512B STG.128.cs), subtile s+1's cp.async loads are
// in flight. 2 x 24.6KB buffers = 49KB -> still 4 CTAs/SM.

namespace {
constexpr int HH   = 38;
constexpr int C    = 512;
constexpr int CSUB = 128;        // channels per CTA
constexpr int NCG  = C / CSUB;   // 4
constexpr int NB   = 9;
constexpr int NY   = 2;          // output rows per CTA
constexpr int NR   = NY + 2;     // 4 loaded rows incl. halo
constexpr int WSUB = 10;         // w positions per subtile (last: 8)
constexpr int LWS  = WSUB + 2;   // 12 local cols incl. halo
constexpr int NPOSS = NR * LWS;  // 48 smem positions per subtile
constexpr int THREADS = 512;
constexpr int HW   = HH * HH;    // 1444
constexpr int RS4  = NB * C / 4; // 1152 float4 per (b,y,w)
constexpr int YS4  = HH * RS4;
constexpr int BUF  = NPOSS * CSUB;      // 6144 floats = 24,576 B
constexpr int SMEM_BYTES = 2 * BUF * 4; // 49,152 B
}

__device__ __forceinline__ void cp_async4(float* smem_dst, const float* gsrc) {
    uint32_t sa = (uint32_t)__cvta_generic_to_shared(smem_dst);
    asm volatile("cp.async.ca.shared.global [%0], [%1], 4;\n"
                 :: "r"(sa), "l"(gsrc) : "memory");
}

__device__ __forceinline__ void issue_subtile(
    float* __restrict__ buf, const float* __restrict__ fc,
    int lane, int wid, int cq0, int y0, int w0s)
{
    // Thread owns p = lane + 32k (k<2, p<48), sweeps c = wid + 16m (m<8).
    // logical (p, c) at buf[p*128 + 4*((c>>2)^(p&31)) + (c&3)]
    #pragma unroll
    for (int k = 0; k < 2; ++k) {
        if (k == 1 && lane >= NPOSS - 32) break;
        int p  = lane + 32 * k;
        int r  = p / LWS;
        int l  = p - r * LWS;
        int yl = min(max(y0 - 1 + r, 0), HH - 1);
        int xg = min(max(w0s - 1 + l, 0), HH - 1);
        const float* __restrict__ g = fc + yl * HH + xg;
        const int swk = (p << 7) + (wid & 3);
        #pragma unroll
        for (int m = 0; m < 8; ++m) {
            int sw = swk + (((cq0 + 4 * m) ^ (p & 31)) << 2);
            cp_async4(&buf[sw], g + m * 16 * HW);
        }
    }
    asm volatile("cp.async.commit_group;\n" ::: "memory");
}

__global__ __launch_bounds__(THREADS, 4)
void spatialpool_kernel(const float* __restrict__ fm, float* __restrict__ out) {
    extern __shared__ float smP[];   // 2 * BUF floats

    const int lane = threadIdx.x & 31;
    const int wid  = threadIdx.x >> 5;
    const int cq0  = wid >> 2;

    const int cg = blockIdx.x;           // channel group 0..3
    const int y0 = blockIdx.y * NY;
    const int b  = blockIdx.z;

    const float* __restrict__ fc =
        fm + ((size_t)b * C + (size_t)cg * CSUB) * HW + (size_t)wid * HW;

    float4* __restrict__ out4 = (float4*)out;
    const size_t rowbase =
        ((size_t)b * HW + (size_t)y0 * HH) * (size_t)RS4
        + (size_t)cg * (CSUB / 4) + lane;

    // Prologue: subtiles 0 and 1 in flight.
    issue_subtile(&smP[0],   fc, lane, wid, cq0, y0, 0);
    issue_subtile(&smP[BUF], fc, lane, wid, cq0, y0, WSUB);

    #pragma unroll 1
    for (int s = 0; s < 4; ++s) {
        if (s < 3) asm volatile("cp.async.wait_group 1;\n" ::: "memory");
        else       asm volatile("cp.async.wait_group 0;\n" ::: "memory");
        __syncthreads();

        const float* __restrict__ buf = &smP[(s & 1) * BUF];
        const int wt = (s == 3) ? 8 : WSUB;
        const size_t sbase = rowbase + (size_t)(s * WSUB) * RS4;

        // R7-verbatim write: n-major, conflict-free LDS.128 + STG.128.cs
        #pragma unroll
        for (int n = 0; n < NB; ++n) {
            const int di = n / 3;
            const int dj = n - di * 3;
            #pragma unroll 2
            for (int q = wid; q < NY * WSUB; q += THREADS / 32) {
                int o  = (q >= wt) ? 1 : 0;
                int wl = q - wt * o;
                if (q >= 2 * wt) break;          // s==3 tail (16 of 20)
                int pos = (o + di) * LWS + wl + dj;

                const float4 v = *(const float4*)
                    &buf[(pos << 7) + ((lane ^ (pos & 31)) << 2)];
                __stcs(&out4[sbase + (size_t)o * YS4
                             + (size_t)wl * RS4 + n * (C / 4)], v);
            }
        }

        if (s < 2) {
            __syncthreads();   // all warps done reading buf before refill
            issue_subtile(&smP[(s & 1) * BUF], fc, lane, wid, cq0,
                          y0, (s + 2) * WSUB);
        }
    }
}

extern "C" void kernel_launch(void* const* d_in, const int* in_sizes, int n_in,
                              void* d_out, int out_size) {
    const float* fm = (const float*)d_in[0];
    float* out = (float*)d_out;
    (void)in_sizes; (void)n_in; (void)out_size;

    cudaFuncSetAttribute(spatialpool_kernel,
                         cudaFuncAttributeMaxDynamicSharedMemorySize,
                         SMEM_BYTES);

    dim3 grid(NCG, HH / NY, 16);   // (4, 19, 16) = 1216 CTAs
    spatialpool_kernel<<<grid, THREADS, SMEM_BYTES>>>(fm, out);
}

// round 17
// speedup vs baseline: 1.5832x; 1.0953x over previous
#include <cuda_runtime.h>
#include <cstdint>

// SpatialPool: fm [B=16, C=512, H=38, W=38] f32 (NCHW)
//   -> out [B, H*W, 9*C] f32, out[b, h*W+w, (di*3+dj)*C + c]
//      = fm[b, c, clamp(h+di-1), clamp(w+dj-1)]  (replicate pad)
//
// R17 = R7 (best, 79.6us) with exactly ONE change: plain write-back STG
// instead of __stcs. Theory: .cs evict-first forces DRAM writebacks in
// exact store-issue order (interleaved 512B pieces from ~24 CTAs); default
// write-back lets the 126MB L2 aggregate dirty lines per DRAM page before
// eviction. Everything else byte-identical to R7.

namespace {
constexpr int HH   = 38;
constexpr int C    = 512;
constexpr int CSUB = 128;        // channels per CTA
constexpr int NCG  = C / CSUB;   // 4
constexpr int NB   = 9;
constexpr int WT   = 19;         // w positions per CTA
constexpr int LW   = WT + 2;     // 21 local cols incl. halo
constexpr int NY   = 2;          // output rows per CTA
constexpr int NR   = NY + 2;     // 4 loaded rows incl. halo
constexpr int NPOS = NR * LW;    // 84 smem positions
constexpr int THREADS = 512;
constexpr int HW   = HH * HH;    // 1444
constexpr int RS4  = NB * C / 4; // 1152 float4 per (b,y,w)
constexpr int YS4  = HH * RS4;   // float4 stride for y+1
}

__device__ __forceinline__ void cp_async4(float* smem_dst, const float* gsrc) {
    uint32_t sa = (uint32_t)__cvta_generic_to_shared(smem_dst);
    asm volatile("cp.async.ca.shared.global [%0], [%1], 4;\n"
                 :: "r"(sa), "l"(gsrc) : "memory");
}

__global__ __launch_bounds__(THREADS, 4)
void spatialpool_kernel(const float* __restrict__ fm, float* __restrict__ out) {
    // logical (pos, c) at smP[pos*128 + 4*((c>>2)^(pos&31)) + (c&3)]
    __shared__ float smP[NPOS * CSUB];   // 43,008 B

    const int lane = threadIdx.x & 31;
    const int wid  = threadIdx.x >> 5;

    const int wh = blockIdx.x & 1;
    const int cg = blockIdx.x >> 1;        // channel group 0..3
    const int w0 = wh * WT;
    const int y0 = blockIdx.y * NY;        // first output row
    const int b  = blockIdx.z;

    const float* __restrict__ fb =
        fm + ((size_t)b * C + (size_t)cg * CSUB) * HW;

    // ---- Load (R7): thread owns p = lane + 32k, sweeps c = wid + 16m.
    // Offset computed once per p; channel stride folded into LDGSTS
    // immediates. Lanes sweep consecutive p -> coalesced. ----
    {
        const float* __restrict__ fc = fb + (size_t)wid * HW;  // c0 = wid
        const int c3  = wid & 3;
        const int cq0 = wid >> 2;
        #pragma unroll
        for (int k = 0; k < 3; ++k) {
            int p = lane + 32 * k;
            if (k == 2 && p >= NPOS) break;
            int r  = p / LW;
            int l  = p - r * LW;
            int yl = min(max(y0 - 1 + r, 0), HH - 1);
            int xg = min(max(w0 - 1 + l, 0), HH - 1);
            const float* __restrict__ g = fc + yl * HH + xg;
            const int swk = (p << 7) + c3;
            #pragma unroll
            for (int m = 0; m < 8; ++m) {
                int sw = swk + (((cq0 + 4 * m) ^ lane) << 2);
                cp_async4(&smP[sw], g + m * 16 * HW);
            }
        }
    }
    asm volatile("cp.async.wait_all;\n" ::: "memory");
    __syncthreads();

    // ---- Write (R7): n-major warp-per-chunk; one conflict-free LDS.128
    // + one coalesced 512B STG.128 per chunk. Plain write-back stores. ----
    float4* __restrict__ out4 = (float4*)out;
    const size_t rowbase =
        ((size_t)b * HW + (size_t)y0 * HH + w0) * (size_t)RS4
        + (size_t)cg * (CSUB / 4) + lane;

    #pragma unroll
    for (int n = 0; n < NB; ++n) {
        const int di = n / 3;
        const int dj = n - di * 3;
        #pragma unroll 3
        for (int q = wid; q < NY * WT; q += THREADS / 32) {
            int o   = (q >= WT) ? 1 : 0;
            int wl  = q - WT * o;
            int pos = (o + di) * LW + wl + dj;

            const float4 v = *(const float4*)
                &smP[(pos << 7) + ((lane ^ (pos & 31)) << 2)];
            out4[rowbase + (size_t)o * YS4
                 + (size_t)wl * RS4 + n * (C / 4)] = v;
        }
    }
}

extern "C" void kernel_launch(void* const* d_in, const int* in_sizes, int n_in,
                              void* d_out, int out_size) {
    const float* fm = (const float*)d_in[0];
    float* out = (float*)d_out;
    (void)in_sizes; (void)n_in; (void)out_size;

    dim3 grid(2 * NCG, HH / NY, 16);   // (8, 19, 16) = 2432 CTAs
    spatialpool_kernel<<<grid, THREADS>>>(fm, out);
}